// round 16
// baseline (speedup 1.0000x reference)
#include <cuda_runtime.h>
#include <cuda_bf16.h>
#include <cstdint>

// GMM: out[m] = sum_n w[n]*coef*exp(-(|x|^2+|mu|^2-2 x.mu)/2)
// R16: R14 (bf16 k16, f32 acc — the measured-fastest MMA config; dtype/occ
// scans R7/R9/R13/R15 all confirm a flat ~12cyc/MMA issue floor) with the
// prep kernel FUSED in: means converted by all 148 CTAs + monotonic-ticket
// grid barrier (one-wave grid, replay-safe), x converted fp32->bf16 straight
// into smem (2 panels, no g_x, no x DMA, boundary stall-free).

#define M_DIM 16384
#define N_DIM 8192
#define NCTA 148
#define NTASK 8192                          // 128 mtiles x 64 chunks
#define NSTAGE 4
#define COEF 0.15915494309189535f           // 1/(2*pi)
#define LOG2E_F 1.4426950408889634f
#define NHL (-0.72134752044448170368f)      // -0.5*log2(e)

// Pre-swizzled bf16 means panels: [block][128 rows][256B], 32KB/block.
__device__ __align__(128) char g_m[(N_DIM / 128) * 32768];   // 2 MB
__device__ __align__(16) float2 g_bw[N_DIM]; // (-0.5*log2e*|mu_n|^2, w_n*coef)
__device__ float g_part[NCTA * 2 * 128];     // per-CTA per-segment partials
__device__ unsigned long long g_ctr;         // monotonic grid-barrier ticket

// ---------------- smem layout (bytes) ----------------
#define MB_S    0                            // 4 stage mbarriers
#define OFF_BW  64                           // 4 slots x 1024B -> ends 4160
#define OFF_RED 4224                         // 1KB reduce scratch
#define OFF_AX  5248                         // 2 x 512B ax slots
#define OFF_X0  6272                         // x panel seg0, 32KB
#define OFF_X1  (OFF_X0 + 32768)             // x panel seg1, 32KB
#define OFF_M   (OFF_X1 + 32768)             // 4 stage bufs x 32KB
#define SMEM_BYTES (OFF_M + NSTAGE * 32768)  // 202880

// ---------------- helpers ----------------
__device__ __forceinline__ uint32_t smem_u32(const void* p) {
    uint32_t a;
    asm("{ .reg .u64 t; cvta.to.shared.u64 t, %1; cvt.u32.u64 %0, t; }" : "=r"(a) : "l"(p));
    return a;
}
__device__ __forceinline__ void mbar_init(uint32_t addr, uint32_t cnt) {
    asm volatile("mbarrier.init.shared.b64 [%0], %1;" :: "r"(addr), "r"(cnt) : "memory");
}
__device__ __forceinline__ void mbar_expect(uint32_t addr, uint32_t bytes) {
    asm volatile("mbarrier.arrive.expect_tx.shared.b64 _, [%0], %1;"
                 :: "r"(addr), "r"(bytes) : "memory");
}
__device__ __forceinline__ void mbar_wait(uint32_t addr, uint32_t parity) {
    asm volatile(
        "{\n\t.reg .pred P;\n"
        "WL_%=:\n\t"
        "mbarrier.try_wait.parity.shared.b64 P, [%0], %1;\n\t"
        "@!P bra WL_%=;\n\t}"
        :: "r"(addr), "r"(parity) : "memory");
}
__device__ __forceinline__ void bulk_g2s(uint32_t dst, const void* src,
                                         uint32_t bytes, uint32_t mbar) {
    asm volatile(
        "cp.async.bulk.shared::cluster.global.mbarrier::complete_tx::bytes "
        "[%0], [%1], %2, [%3];"
        :: "r"(dst), "l"(src), "r"(bytes), "r"(mbar) : "memory");
}
__device__ __forceinline__ void ldsm4(uint32_t& r0, uint32_t& r1, uint32_t& r2,
                                      uint32_t& r3, uint32_t addr) {
    asm volatile("ldmatrix.sync.aligned.m8n8.x4.shared.b16 {%0,%1,%2,%3}, [%4];"
                 : "=r"(r0), "=r"(r1), "=r"(r2), "=r"(r3) : "r"(addr));
}
__device__ __forceinline__ void mma16816(float& c0, float& c1, float& c2, float& c3,
                                         uint32_t a0, uint32_t a1, uint32_t a2, uint32_t a3,
                                         uint32_t b0, uint32_t b1) {
    asm volatile(
        "mma.sync.aligned.m16n8k16.row.col.f32.bf16.bf16.f32 "
        "{%0,%1,%2,%3}, {%4,%5,%6,%7}, {%8,%9}, {%0,%1,%2,%3};"
        : "+f"(c0), "+f"(c1), "+f"(c2), "+f"(c3)
        : "r"(a0), "r"(a1), "r"(a2), "r"(a3), "r"(b0), "r"(b1));
}
__device__ __forceinline__ void mma16816_z(float& c0, float& c1, float& c2, float& c3,
                                           uint32_t a0, uint32_t a1, uint32_t a2, uint32_t a3,
                                           uint32_t b0, uint32_t b1) {
    asm volatile(
        "mma.sync.aligned.m16n8k16.row.col.f32.bf16.bf16.f32 "
        "{%0,%1,%2,%3}, {%4,%5,%6,%7}, {%8,%9}, {%10,%10,%10,%10};"
        : "=f"(c0), "=f"(c1), "=f"(c2), "=f"(c3)
        : "r"(a0), "r"(a1), "r"(a2), "r"(a3), "r"(b0), "r"(b1), "f"(0.f));
}
__device__ __forceinline__ float ex2_pred(float arg) {
    float e = 0.f;
    asm("{\n\t.reg .pred p;\n\t"
        "setp.gt.f32 p, %1, 0fC2FC0000;\n\t"
        "@p ex2.approx.ftz.f32 %0, %1;\n\t}"
        : "+f"(e) : "f"(arg));
    return e;
}
__device__ __forceinline__ uint32_t pkbf(__nv_bfloat16 a, __nv_bfloat16 b) {
    __nv_bfloat162 t(a, b);
    return *reinterpret_cast<uint32_t*>(&t);
}

// ---------------- main fused kernel (persistent, balanced, self-prepping) ----
// 148 CTAs x 256 threads. Warp grid 4m x 2n, warp tile 32m x 64n.
__global__ __launch_bounds__(256, 1) void gmm_mma(const float* __restrict__ x,
                                                  const float* __restrict__ means,
                                                  const float* __restrict__ w) {
    extern __shared__ char smem[];
    const uint32_t sb = smem_u32(smem);
    const int tid = threadIdx.x, wid = tid >> 5, lane = tid & 31;
    const int wm = wid >> 1, wn = wid & 1;

    const int cta = blockIdx.x;
    const uint32_t t0 = (uint32_t)(cta * NTASK) / NCTA;
    const uint32_t t1 = (uint32_t)((cta + 1) * NTASK) / NCTA;
    const int J = (int)(t1 - t0);
    const int mt0 = (int)(t0 >> 6), mt1 = (int)((t1 - 1) >> 6);
    const int c0 = (int)(t0 & 63);
    const bool twoseg = (mt1 > mt0);
    const int len0 = twoseg ? (64 - c0) : J;
#define CHUNK(j) ((j) < len0 ? c0 + (j) : (j) - len0)

    if (tid == 0) {
#pragma unroll
        for (int s = 0; s < NSTAGE; s++) mbar_init(sb + MB_S + s * 8, 1);
    }

    // ---- Phase A: convert this CTA's means slice -> g_m / g_bw ----
    {
        const int mr0 = (int)((uint32_t)(cta * N_DIM) / NCTA);
        const int mr1 = (int)((uint32_t)((cta + 1) * N_DIM) / NCTA);
        for (int row = mr0 + wid; row < mr1; row += 8) {
            float4 v = reinterpret_cast<const float4*>(means)[(size_t)row * 32 + lane];
            float s = v.x * v.x + v.y * v.y + v.z * v.z + v.w * v.w;
            uint2 hv = make_uint2(pkbf(__float2bfloat16_rn(v.x), __float2bfloat16_rn(v.y)),
                                  pkbf(__float2bfloat16_rn(v.z), __float2bfloat16_rn(v.w)));
            int r = row & 127;
            uint32_t off = (uint32_t)r * 256
                         + (((uint32_t)(lane >> 1) * 16) ^ (((uint32_t)r & 7) << 4))
                         + (uint32_t)(lane & 1) * 8;
            *reinterpret_cast<uint2*>(g_m + (size_t)(row >> 7) * 32768 + off) = hv;
#pragma unroll
            for (int o = 16; o; o >>= 1) s += __shfl_down_sync(0xffffffffu, s, o);
            if (lane == 0) g_bw[row] = make_float2(NHL * s, w[row] * COEF);
        }
    }
    __threadfence();     // publish means writes
    __syncthreads();     // all warps of this CTA done (mbar_init also visible)

    // ---- take grid-barrier ticket (monotonic counter: replay-safe) ----
    __shared__ unsigned long long s_target;
    if (tid == 0) {
        unsigned long long t = atomicAdd(&g_ctr, 1ULL);
        s_target = (t / NCTA + 1ULL) * NCTA;
    }

    // ---- Phase B: convert x panels fp32 -> bf16 directly into smem ----
    float* axs = reinterpret_cast<float*>(smem + OFF_AX);
    {
#pragma unroll
        for (int p = 0; p < 2; p++) {
            if (p == 1 && !twoseg) break;
            const int mt = p ? mt1 : mt0;
            char* dst = smem + (p ? OFF_X1 : OFF_X0);
            for (int r = wid; r < 128; r += 8) {
                float4 v = reinterpret_cast<const float4*>(x)[(size_t)(mt * 128 + r) * 32 + lane];
                float s = v.x * v.x + v.y * v.y + v.z * v.z + v.w * v.w;
                uint2 hv = make_uint2(pkbf(__float2bfloat16_rn(v.x), __float2bfloat16_rn(v.y)),
                                      pkbf(__float2bfloat16_rn(v.z), __float2bfloat16_rn(v.w)));
                uint32_t off = (uint32_t)r * 256
                             + (((uint32_t)(lane >> 1) * 16) ^ (((uint32_t)r & 7) << 4))
                             + (uint32_t)(lane & 1) * 8;
                *reinterpret_cast<uint2*>(dst + off) = hv;
#pragma unroll
                for (int o = 16; o; o >>= 1) s += __shfl_down_sync(0xffffffffu, s, o);
                if (lane == 0) axs[p * 128 + r] = NHL * s;
            }
        }
    }
    __syncthreads();     // s_target visible; x panels + ax complete

    // ---- wait for all CTAs' means conversion, then start the pipeline ----
    if (tid == 0) {
        unsigned long long cur;
        do {
            asm volatile("ld.global.acquire.gpu.u64 %0, [%1];"
                         : "=l"(cur) : "l"(&g_ctr) : "memory");
        } while (cur < s_target);
#pragma unroll
        for (int s = 0; s < NSTAGE; s++) {
            const int cn = CHUNK(s);
            mbar_expect(sb + MB_S + s * 8, 33792);
            bulk_g2s(sb + OFF_M + s * 32768, g_m + (size_t)cn * 32768, 32768, sb + MB_S + s * 8);
            bulk_g2s(sb + OFF_BW + s * 1024, (const char*)g_bw + (size_t)cn * 1024, 1024,
                     sb + MB_S + s * 8);
        }
    }
    __syncthreads();

    const uint32_t sx = (uint32_t)((lane & 7) << 4);
    const uint32_t h16 = (uint32_t)((lane >> 4) * 16);
    const uint32_t aOff = (uint32_t)((wm * 32 + (lane & 15)) * 256);
    const uint32_t bLin = (uint32_t)((wn * 64 + (lane & 15)) * 256);
    const int bwIdx = wn * 32 + (lane & 3);
    float* red = reinterpret_cast<float*>(smem + OFF_RED);

    float axv[4], s[4] = {0.f, 0.f, 0.f, 0.f};
    uint32_t ah[8][2][4];
    uint32_t phmask = 0;

#define LOAD_AX(P)                                                            \
    {                                                                         \
        _Pragma("unroll")                                                     \
        for (int mtl = 0; mtl < 2; mtl++)                                     \
            _Pragma("unroll")                                                 \
            for (int h = 0; h < 2; h++)                                       \
                axv[mtl * 2 + h] =                                            \
                    axs[(P) * 128 + wm * 32 + mtl * 16 + h * 8 + (lane >> 2)]; \
    }
#define LOAD_A(BASE)                                                          \
    {                                                                         \
        _Pragma("unroll")                                                     \
        for (int ks = 0; ks < 8; ks++) {                                      \
            const uint32_t ko = ((uint32_t)(ks * 32) + h16) ^ sx;             \
            _Pragma("unroll")                                                 \
            for (int mtl = 0; mtl < 2; mtl++)                                 \
                ldsm4(ah[ks][mtl][0], ah[ks][mtl][1], ah[ks][mtl][2],         \
                      ah[ks][mtl][3], (BASE) + aOff + (uint32_t)(mtl * 4096) + ko); \
        }                                                                     \
    }
#define FLUSH(IDX)                                                            \
    {                                                                         \
        _Pragma("unroll")                                                     \
        for (int k = 0; k < 4; k++) {                                         \
            s[k] += __shfl_xor_sync(0xffffffffu, s[k], 1);                    \
            s[k] += __shfl_xor_sync(0xffffffffu, s[k], 2);                    \
        }                                                                     \
        __syncthreads();                                                      \
        if ((lane & 3) == 0) {                                                \
            _Pragma("unroll")                                                 \
            for (int mtl = 0; mtl < 2; mtl++)                                 \
                _Pragma("unroll")                                             \
                for (int h = 0; h < 2; h++) {                                 \
                    int row = wm * 32 + mtl * 16 + h * 8 + (lane >> 2);       \
                    red[row * 2 + wn] = s[mtl * 2 + h];                       \
                }                                                             \
        }                                                                     \
        __syncthreads();                                                      \
        if (tid < 128) g_part[(IDX) * 128 + tid] = red[tid * 2] + red[tid * 2 + 1]; \
        s[0] = s[1] = s[2] = s[3] = 0.f;                                      \
    }

    LOAD_A(sb + OFF_X0);
    LOAD_AX(0);

    for (int j = 0; j < J; j++) {
        if (twoseg && j == len0) {   // segment boundary: flush + switch panel
            FLUSH(cta * 2);
            LOAD_A(sb + OFF_X1);
            LOAD_AX(1);
        }
        const int st = j & (NSTAGE - 1);
        mbar_wait(sb + MB_S + st * 8, (phmask >> st) & 1);
        phmask ^= 1u << st;

        float acc[64];
        const uint32_t pb = sb + OFF_M + st * 32768 + bLin;
#pragma unroll
        for (int ks = 0; ks < 8; ks++) {
            const uint32_t ko = ((uint32_t)(ks * 32) + h16) ^ sx;
            uint32_t bf[4][4];
#pragma unroll
            for (int np = 0; np < 4; np++)
                ldsm4(bf[np][0], bf[np][1], bf[np][2], bf[np][3], pb + np * 4096 + ko);
#pragma unroll
            for (int mtl = 0; mtl < 2; mtl++)
#pragma unroll
                for (int np = 0; np < 4; np++) {
                    float* cc0 = &acc[(mtl * 8 + np * 2) * 4];
                    float* cc1 = &acc[(mtl * 8 + np * 2 + 1) * 4];
                    if (ks == 0) {
                        mma16816_z(cc0[0], cc0[1], cc0[2], cc0[3],
                                   ah[ks][mtl][0], ah[ks][mtl][1],
                                   ah[ks][mtl][2], ah[ks][mtl][3],
                                   bf[np][0], bf[np][2]);
                        mma16816_z(cc1[0], cc1[1], cc1[2], cc1[3],
                                   ah[ks][mtl][0], ah[ks][mtl][1],
                                   ah[ks][mtl][2], ah[ks][mtl][3],
                                   bf[np][1], bf[np][3]);
                    } else {
                        mma16816(cc0[0], cc0[1], cc0[2], cc0[3],
                                 ah[ks][mtl][0], ah[ks][mtl][1],
                                 ah[ks][mtl][2], ah[ks][mtl][3],
                                 bf[np][0], bf[np][2]);
                        mma16816(cc1[0], cc1[1], cc1[2], cc1[3],
                                 ah[ks][mtl][0], ah[ks][mtl][1],
                                 ah[ks][mtl][2], ah[ks][mtl][3],
                                 bf[np][1], bf[np][3]);
                    }
                }
        }

        // fused epilogue (bw slot st still valid; refill comes after the sync)
        const float4* bwp = reinterpret_cast<const float4*>(smem + OFF_BW + st * 1024);
#pragma unroll
        for (int nt = 0; nt < 8; nt++) {
            float4 bw4 = bwp[bwIdx + nt * 4];
#pragma unroll
            for (int mtl = 0; mtl < 2; mtl++)
#pragma unroll
                for (int h = 0; h < 2; h++) {
                    float d0 = acc[(mtl * 8 + nt) * 4 + h * 2];
                    float d1 = acc[(mtl * 8 + nt) * 4 + h * 2 + 1];
                    float base = axv[mtl * 2 + h];
                    float e0 = ex2_pred(fmaf(LOG2E_F, d0, base + bw4.x));
                    float e1 = ex2_pred(fmaf(LOG2E_F, d1, base + bw4.z));
                    s[mtl * 2 + h] = fmaf(bw4.y, e0, s[mtl * 2 + h]);
                    s[mtl * 2 + h] = fmaf(bw4.w, e1, s[mtl * 2 + h]);
                }
        }

        __syncthreads();             // stage st fully consumed by all warps
        if (tid == 0 && j + NSTAGE < J) {
            const int cn = CHUNK(j + NSTAGE);
            const uint32_t mb = sb + MB_S + st * 8;
            mbar_expect(mb, 33792);
            bulk_g2s(sb + OFF_M + st * 32768, g_m + (size_t)cn * 32768, 32768, mb);
            bulk_g2s(sb + OFF_BW + st * 1024, (const char*)g_bw + (size_t)cn * 1024, 1024, mb);
        }
    }

    FLUSH(cta * 2 + (twoseg ? 1 : 0));
}

// ---------------- reduce: recombine per-CTA partials -> out ----------------
__global__ void reduce_out(float* __restrict__ out) {
    const int mt = blockIdx.x;         // 128 mtiles
    const int r = threadIdx.x;         // 128 rows
    const uint32_t mtStart = (uint32_t)mt * 64, mtEnd = mtStart + 64;
    const int w = (mt * 37) >> 5;      // ~ mt*NCTA/128
    float sum = 0.f;
    const int clo = w - 2 < 0 ? 0 : w - 2;
    const int chi = w + 3 > NCTA - 1 ? NCTA - 1 : w + 3;
    for (int c = clo; c <= chi; c++) {
        uint32_t s0 = (uint32_t)(c * NTASK) / NCTA;
        uint32_t e0 = (uint32_t)((c + 1) * NTASK) / NCTA;
        if (s0 < mtEnd && e0 > mtStart) {
            int seg = ((int)(s0 >> 6) == mt) ? 0 : 1;
            sum += g_part[(c * 2 + seg) * 128 + r];
        }
    }
    out[mt * 128 + r] = sum;
}

// ---------------------------------------------------------------------------
extern "C" void kernel_launch(void* const* d_in, const int* in_sizes, int n_in,
                              void* d_out, int out_size) {
    const float* x = (const float*)d_in[0];      // [16384, 128]
    const float* means = (const float*)d_in[1];  // [8192, 128]
    const float* w = (const float*)d_in[2];      // [8192]
    float* out = (float*)d_out;                  // [16384]
    (void)in_sizes; (void)n_in; (void)out_size;

    cudaFuncSetAttribute(gmm_mma, cudaFuncAttributeMaxDynamicSharedMemorySize, SMEM_BYTES);

    gmm_mma<<<NCTA, 256, SMEM_BYTES>>>(x, means, w);
    reduce_out<<<128, 128>>>(out);
}

// round 17
// speedup vs baseline: 1.0562x; 1.0562x over previous
#include <cuda_runtime.h>
#include <cuda_bf16.h>
#include <cstdint>

// GMM: out[m] = sum_n w[n]*coef*exp(-(|x|^2+|mu|^2-2 x.mu)/2)
// R17: R14 (bf16 k16 mma.sync at its ~96us issue floor; 148-CTA balanced
// persistent slices, 4-stage bulk-DMA pipeline, fused predicated-ex2
// epilogue) with reduce_out FOLDED into the main kernel tail: last-writer
// CTA per mtile (atomic counter, prep-zeroed each replay) sums partials in
// fixed CTA order (deterministic) and writes out. Removes a 5.4us launch.

#define M_DIM 16384
#define N_DIM 8192
#define NCTA 148
#define NTASK 8192                          // 128 mtiles x 64 chunks
#define NSTAGE 4
#define COEF 0.15915494309189535f           // 1/(2*pi)
#define LOG2E_F 1.4426950408889634f
#define NHL (-0.72134752044448170368f)      // -0.5*log2(e)

// Pre-swizzled bf16 panels: [block][128 rows][256B], 32KB/block.
__device__ __align__(128) char g_x[(M_DIM / 128) * 32768];   // 4 MB
__device__ __align__(128) char g_m[(N_DIM / 128) * 32768];   // 2 MB
__device__ float g_ax[M_DIM];                // -0.5*log2e*|x_m|^2
__device__ __align__(16) float2 g_bw[N_DIM]; // (-0.5*log2e*|mu_n|^2, w_n*coef)
__device__ float g_part[NCTA * 2 * 128];     // per-CTA per-segment partials
__device__ unsigned g_cnt[128];              // per-mtile writer counters

// ---------------- smem layout (bytes) ----------------
#define MB_S    0                            // 4 stage mbarriers
#define MB_X    32
#define OFF_BW  64                           // 4 slots x 1024B -> ends 4160
#define OFF_RED 4224                         // 1KB reduce scratch
#define OFF_X   5376                         // x panel 32KB
#define OFF_M   38144                        // 4 stage bufs x 32KB
#define SMEM_BYTES (OFF_M + NSTAGE * 32768)  // 169216

// ---------------- helpers ----------------
__device__ __forceinline__ uint32_t smem_u32(const void* p) {
    uint32_t a;
    asm("{ .reg .u64 t; cvta.to.shared.u64 t, %1; cvt.u32.u64 %0, t; }" : "=r"(a) : "l"(p));
    return a;
}
__device__ __forceinline__ void mbar_init(uint32_t addr, uint32_t cnt) {
    asm volatile("mbarrier.init.shared.b64 [%0], %1;" :: "r"(addr), "r"(cnt) : "memory");
}
__device__ __forceinline__ void mbar_expect(uint32_t addr, uint32_t bytes) {
    asm volatile("mbarrier.arrive.expect_tx.shared.b64 _, [%0], %1;"
                 :: "r"(addr), "r"(bytes) : "memory");
}
__device__ __forceinline__ void mbar_wait(uint32_t addr, uint32_t parity) {
    asm volatile(
        "{\n\t.reg .pred P;\n"
        "WL_%=:\n\t"
        "mbarrier.try_wait.parity.shared.b64 P, [%0], %1;\n\t"
        "@!P bra WL_%=;\n\t}"
        :: "r"(addr), "r"(parity) : "memory");
}
__device__ __forceinline__ void bulk_g2s(uint32_t dst, const void* src,
                                         uint32_t bytes, uint32_t mbar) {
    asm volatile(
        "cp.async.bulk.shared::cluster.global.mbarrier::complete_tx::bytes "
        "[%0], [%1], %2, [%3];"
        :: "r"(dst), "l"(src), "r"(bytes), "r"(mbar) : "memory");
}
__device__ __forceinline__ void ldsm4(uint32_t& r0, uint32_t& r1, uint32_t& r2,
                                      uint32_t& r3, uint32_t addr) {
    asm volatile("ldmatrix.sync.aligned.m8n8.x4.shared.b16 {%0,%1,%2,%3}, [%4];"
                 : "=r"(r0), "=r"(r1), "=r"(r2), "=r"(r3) : "r"(addr));
}
__device__ __forceinline__ void mma16816(float& c0, float& c1, float& c2, float& c3,
                                         uint32_t a0, uint32_t a1, uint32_t a2, uint32_t a3,
                                         uint32_t b0, uint32_t b1) {
    asm volatile(
        "mma.sync.aligned.m16n8k16.row.col.f32.bf16.bf16.f32 "
        "{%0,%1,%2,%3}, {%4,%5,%6,%7}, {%8,%9}, {%0,%1,%2,%3};"
        : "+f"(c0), "+f"(c1), "+f"(c2), "+f"(c3)
        : "r"(a0), "r"(a1), "r"(a2), "r"(a3), "r"(b0), "r"(b1));
}
__device__ __forceinline__ void mma16816_z(float& c0, float& c1, float& c2, float& c3,
                                           uint32_t a0, uint32_t a1, uint32_t a2, uint32_t a3,
                                           uint32_t b0, uint32_t b1) {
    asm volatile(
        "mma.sync.aligned.m16n8k16.row.col.f32.bf16.bf16.f32 "
        "{%0,%1,%2,%3}, {%4,%5,%6,%7}, {%8,%9}, {%10,%10,%10,%10};"
        : "=f"(c0), "=f"(c1), "=f"(c2), "=f"(c3)
        : "r"(a0), "r"(a1), "r"(a2), "r"(a3), "r"(b0), "r"(b1), "f"(0.f));
}
__device__ __forceinline__ float ex2_pred(float arg) {
    float e = 0.f;
    asm("{\n\t.reg .pred p;\n\t"
        "setp.gt.f32 p, %1, 0fC2FC0000;\n\t"
        "@p ex2.approx.ftz.f32 %0, %1;\n\t}"
        : "+f"(e) : "f"(arg));
    return e;
}
__device__ __forceinline__ uint32_t pkbf(__nv_bfloat16 a, __nv_bfloat16 b) {
    __nv_bfloat162 t(a, b);
    return *reinterpret_cast<uint32_t*>(&t);
}
// number of CTAs whose task range intersects mtile mt (matches slice formula)
__device__ __forceinline__ int n_writers(int mt) {
    const uint32_t mtStart = (uint32_t)mt * 64, mtEnd = mtStart + 64;
    const int w = (mt * 37) >> 5;
    const int clo = w - 2 < 0 ? 0 : w - 2;
    const int chi = w + 3 > NCTA - 1 ? NCTA - 1 : w + 3;
    int cnt = 0;
    for (int c = clo; c <= chi; c++) {
        uint32_t s0 = (uint32_t)(c * NTASK) / NCTA;
        uint32_t e0 = (uint32_t)((c + 1) * NTASK) / NCTA;
        if (s0 < mtEnd && e0 > mtStart) cnt++;
    }
    return cnt;
}

// ---------------- merged prologue: fp32 -> bf16 (pre-swizzled), norms --------
__global__ void prep(const float* __restrict__ x, const float* __restrict__ means,
                     const float* __restrict__ w) {
    if (blockIdx.x == 0 && threadIdx.x < 128) g_cnt[threadIdx.x] = 0;
    int gr = blockIdx.x * 8 + (threadIdx.x >> 5);
    int lane = threadIdx.x & 31;
    const bool is_x = gr < M_DIM;
    int row = is_x ? gr : gr - M_DIM;
    const float* src = (is_x ? x : means) + (size_t)row * 128;
    char* dstb = (is_x ? g_x : g_m) + (size_t)(row >> 7) * 32768;
    int r = row & 127;

    float4 v = reinterpret_cast<const float4*>(src)[lane];
    float s = v.x * v.x + v.y * v.y + v.z * v.z + v.w * v.w;
    uint2 hv = make_uint2(pkbf(__float2bfloat16_rn(v.x), __float2bfloat16_rn(v.y)),
                          pkbf(__float2bfloat16_rn(v.z), __float2bfloat16_rn(v.w)));
    uint32_t off = (uint32_t)r * 256
                 + (((uint32_t)(lane >> 1) * 16) ^ (((uint32_t)r & 7) << 4))
                 + (uint32_t)(lane & 1) * 8;
    *reinterpret_cast<uint2*>(dstb + off) = hv;
#pragma unroll
    for (int o = 16; o; o >>= 1) s += __shfl_down_sync(0xffffffffu, s, o);
    if (lane == 0) {
        if (is_x) g_ax[row] = NHL * s;
        else      g_bw[row] = make_float2(NHL * s, w[row] * COEF);
    }
}

// ---------------- main fused kernel (persistent, balanced) ----------------
// 148 CTAs x 256 threads. Warp grid 4m x 2n, warp tile 32m x 64n.
__global__ __launch_bounds__(256, 1) void gmm_mma(float* __restrict__ out) {
    extern __shared__ char smem[];
    const uint32_t sb = smem_u32(smem);
    const int tid = threadIdx.x, wid = tid >> 5, lane = tid & 31;
    const int wm = wid >> 1, wn = wid & 1;

    const int cta = blockIdx.x;
    const uint32_t t0 = (uint32_t)(cta * NTASK) / NCTA;
    const uint32_t t1 = (uint32_t)((cta + 1) * NTASK) / NCTA;
    const int J = (int)(t1 - t0);
    const int mt0 = (int)(t0 >> 6), mt1 = (int)((t1 - 1) >> 6);
    const int c0 = (int)(t0 & 63);
    const bool twoseg = (mt1 > mt0);
    const int len0 = twoseg ? (64 - c0) : J;
#define CHUNK(j) ((j) < len0 ? c0 + (j) : (j) - len0)

    if (tid == 0) {
#pragma unroll
        for (int s = 0; s < NSTAGE; s++) mbar_init(sb + MB_S + s * 8, 1);
        mbar_init(sb + MB_X, 1);
    }
    __syncthreads();
    if (tid == 0) {
        mbar_expect(sb + MB_X, 32768);
        bulk_g2s(sb + OFF_X, g_x + (size_t)mt0 * 32768, 32768, sb + MB_X);
#pragma unroll
        for (int s = 0; s < NSTAGE; s++) {
            const int cn = CHUNK(s);
            mbar_expect(sb + MB_S + s * 8, 33792);
            bulk_g2s(sb + OFF_M + s * 32768, g_m + (size_t)cn * 32768, 32768, sb + MB_S + s * 8);
            bulk_g2s(sb + OFF_BW + s * 1024, (const char*)g_bw + (size_t)cn * 1024, 1024,
                     sb + MB_S + s * 8);
        }
    }

    const uint32_t sx = (uint32_t)((lane & 7) << 4);
    const uint32_t h16 = (uint32_t)((lane >> 4) * 16);
    const uint32_t aLin = sb + OFF_X + (uint32_t)((wm * 32 + (lane & 15)) * 256);
    const uint32_t bLin = (uint32_t)((wn * 64 + (lane & 15)) * 256);
    const int bwIdx = wn * 32 + (lane & 3);
    float* red = reinterpret_cast<float*>(smem + OFF_RED);
    __shared__ int s_last;

    float axv[4], s[4] = {0.f, 0.f, 0.f, 0.f};
    uint32_t ah[8][2][4];
    uint32_t phmask = 0, xph = 0;

    // flush partial for mtile MT (partial slot IDX); last writer reduces -> out
    auto flush = [&](int idx, int mt) {
#pragma unroll
        for (int k = 0; k < 4; k++) {
            s[k] += __shfl_xor_sync(0xffffffffu, s[k], 1);
            s[k] += __shfl_xor_sync(0xffffffffu, s[k], 2);
        }
        __syncthreads();
        if ((lane & 3) == 0) {
#pragma unroll
            for (int mtl = 0; mtl < 2; mtl++)
#pragma unroll
                for (int h = 0; h < 2; h++) {
                    int row = wm * 32 + mtl * 16 + h * 8 + (lane >> 2);
                    red[row * 2 + wn] = s[mtl * 2 + h];
                }
        }
        __syncthreads();
        if (tid < 128) g_part[idx * 128 + tid] = red[tid * 2] + red[tid * 2 + 1];
        __threadfence();
        __syncthreads();
        if (tid == 0) {
            unsigned old = atomicAdd(&g_cnt[mt], 1u);
            s_last = (old + 1 == (unsigned)n_writers(mt));
        }
        __syncthreads();
        if (s_last) {
            __threadfence();
            if (tid < 128) {
                const uint32_t mtStart = (uint32_t)mt * 64, mtEnd = mtStart + 64;
                const int wg = (mt * 37) >> 5;
                const int clo = wg - 2 < 0 ? 0 : wg - 2;
                const int chi = wg + 3 > NCTA - 1 ? NCTA - 1 : wg + 3;
                float sum = 0.f;
                for (int c = clo; c <= chi; c++) {
                    uint32_t s0 = (uint32_t)(c * NTASK) / NCTA;
                    uint32_t e0 = (uint32_t)((c + 1) * NTASK) / NCTA;
                    if (s0 < mtEnd && e0 > mtStart) {
                        int seg = ((int)(s0 >> 6) == mt) ? 0 : 1;
                        sum += g_part[(c * 2 + seg) * 128 + tid];
                    }
                }
                out[mt * 128 + tid] = sum;
            }
        }
        s[0] = s[1] = s[2] = s[3] = 0.f;
    };

#define LOAD_AX(MT)                                                           \
    {                                                                         \
        _Pragma("unroll")                                                     \
        for (int mtl = 0; mtl < 2; mtl++)                                     \
            _Pragma("unroll")                                                 \
            for (int h = 0; h < 2; h++)                                       \
                axv[mtl * 2 + h] =                                            \
                    g_ax[(MT) * 128 + wm * 32 + mtl * 16 + h * 8 + (lane >> 2)]; \
    }
#define LOAD_A()                                                              \
    {                                                                         \
        _Pragma("unroll")                                                     \
        for (int ks = 0; ks < 8; ks++) {                                      \
            const uint32_t ko = ((uint32_t)(ks * 32) + h16) ^ sx;             \
            _Pragma("unroll")                                                 \
            for (int mtl = 0; mtl < 2; mtl++)                                 \
                ldsm4(ah[ks][mtl][0], ah[ks][mtl][1], ah[ks][mtl][2],         \
                      ah[ks][mtl][3], aLin + (uint32_t)(mtl * 4096) + ko);    \
        }                                                                     \
    }

    mbar_wait(sb + MB_X, xph); xph ^= 1;
    LOAD_A();
    __syncthreads();                 // all warps done reading OFF_X
    if (twoseg && tid == 0) {        // prefetch next mtile's x panel now
        mbar_expect(sb + MB_X, 32768);
        bulk_g2s(sb + OFF_X, g_x + (size_t)mt1 * 32768, 32768, sb + MB_X);
    }
    LOAD_AX(mt0);

    for (int j = 0; j < J; j++) {
        if (twoseg && j == len0) {   // segment boundary: flush + switch mtile
            flush(cta * 2, mt0);
            mbar_wait(sb + MB_X, xph); xph ^= 1;
            LOAD_A();
            LOAD_AX(mt1);
        }
        const int st = j & (NSTAGE - 1);
        mbar_wait(sb + MB_S + st * 8, (phmask >> st) & 1);
        phmask ^= 1u << st;

        float acc[64];
        const uint32_t pb = sb + OFF_M + st * 32768 + bLin;
#pragma unroll
        for (int ks = 0; ks < 8; ks++) {
            const uint32_t ko = ((uint32_t)(ks * 32) + h16) ^ sx;
            uint32_t bf[4][4];
#pragma unroll
            for (int np = 0; np < 4; np++)
                ldsm4(bf[np][0], bf[np][1], bf[np][2], bf[np][3], pb + np * 4096 + ko);
#pragma unroll
            for (int mtl = 0; mtl < 2; mtl++)
#pragma unroll
                for (int np = 0; np < 4; np++) {
                    float* cc0 = &acc[(mtl * 8 + np * 2) * 4];
                    float* cc1 = &acc[(mtl * 8 + np * 2 + 1) * 4];
                    if (ks == 0) {
                        mma16816_z(cc0[0], cc0[1], cc0[2], cc0[3],
                                   ah[ks][mtl][0], ah[ks][mtl][1],
                                   ah[ks][mtl][2], ah[ks][mtl][3],
                                   bf[np][0], bf[np][2]);
                        mma16816_z(cc1[0], cc1[1], cc1[2], cc1[3],
                                   ah[ks][mtl][0], ah[ks][mtl][1],
                                   ah[ks][mtl][2], ah[ks][mtl][3],
                                   bf[np][1], bf[np][3]);
                    } else {
                        mma16816(cc0[0], cc0[1], cc0[2], cc0[3],
                                 ah[ks][mtl][0], ah[ks][mtl][1],
                                 ah[ks][mtl][2], ah[ks][mtl][3],
                                 bf[np][0], bf[np][2]);
                        mma16816(cc1[0], cc1[1], cc1[2], cc1[3],
                                 ah[ks][mtl][0], ah[ks][mtl][1],
                                 ah[ks][mtl][2], ah[ks][mtl][3],
                                 bf[np][1], bf[np][3]);
                    }
                }
        }

        // fused epilogue (bw slot st still valid; refill comes after the sync)
        const float4* bwp = reinterpret_cast<const float4*>(smem + OFF_BW + st * 1024);
#pragma unroll
        for (int nt = 0; nt < 8; nt++) {
            float4 bw4 = bwp[bwIdx + nt * 4];
#pragma unroll
            for (int mtl = 0; mtl < 2; mtl++)
#pragma unroll
                for (int h = 0; h < 2; h++) {
                    float d0 = acc[(mtl * 8 + nt) * 4 + h * 2];
                    float d1 = acc[(mtl * 8 + nt) * 4 + h * 2 + 1];
                    float base = axv[mtl * 2 + h];
                    float e0 = ex2_pred(fmaf(LOG2E_F, d0, base + bw4.x));
                    float e1 = ex2_pred(fmaf(LOG2E_F, d1, base + bw4.z));
                    s[mtl * 2 + h] = fmaf(bw4.y, e0, s[mtl * 2 + h]);
                    s[mtl * 2 + h] = fmaf(bw4.w, e1, s[mtl * 2 + h]);
                }
        }

        __syncthreads();             // stage st fully consumed by all warps
        if (tid == 0 && j + NSTAGE < J) {
            const int cn = CHUNK(j + NSTAGE);
            const uint32_t mb = sb + MB_S + st * 8;
            mbar_expect(mb, 33792);
            bulk_g2s(sb + OFF_M + st * 32768, g_m + (size_t)cn * 32768, 32768, mb);
            bulk_g2s(sb + OFF_BW + st * 1024, (const char*)g_bw + (size_t)cn * 1024, 1024, mb);
        }
    }

    flush(cta * 2 + (twoseg ? 1 : 0), twoseg ? mt1 : mt0);
}

// ---------------------------------------------------------------------------
extern "C" void kernel_launch(void* const* d_in, const int* in_sizes, int n_in,
                              void* d_out, int out_size) {
    const float* x = (const float*)d_in[0];      // [16384, 128]
    const float* means = (const float*)d_in[1];  // [8192, 128]
    const float* w = (const float*)d_in[2];      // [8192]
    float* out = (float*)d_out;                  // [16384]
    (void)in_sizes; (void)n_in; (void)out_size;

    cudaFuncSetAttribute(gmm_mma, cudaFuncAttributeMaxDynamicSharedMemorySize, SMEM_BYTES);

    prep<<<(M_DIM + N_DIM) / 8, 256>>>(x, means, w);
    gmm_mma<<<NCTA, 256, SMEM_BYTES>>>(out);
}